// round 1
// baseline (speedup 1.0000x reference)
#include <cuda_runtime.h>
#include <cuda_bf16.h>
#include <cstdint>

// ---------------------------------------------------------------------------
// Direct circular-convolution implementation of Net_CCL.
//
// Shapes:
//   x      : [16,2,64,256] -> treated as [32,64,256] (c_in = 1)
//   L1: conv w1[50,1,3,7]  + b1, maxpool(2,4), relu   -> buf1 [32,50,32,64]
//   L2: conv w2[50,50,3,7] + b2, maxpool(2,4), relu   -> buf2 [32,50,16,16]
//   merge: out[b] = s[2b] + mean(s[2b+1])             -> bufM [16,50,16,16]
//   L3: upsample(2,4) conv w3[50,50,3,5] + b3, relu   -> buf3 [16,50,32,64]
//   L4: upsample(2,4) conv w4[50,50,3,7] + b4, relu   -> buf4 [16,50,64,256]
//   L5: conv w5[1,50,3,7]  + b5, sigmoid              -> out  [16,64,256]
//
// Circular conv: y[i][j] = sum_{p,q} x[(i-p) mod H][(j-q) mod W] * w[p][q]
// Upsampled-input layers read the small pre-upsample tensor directly:
// only taps with p = i (mod 2) and q = j (mod 4) are nonzero.
// ---------------------------------------------------------------------------

__device__ float g_buf1[32 * 50 * 32 * 64];    // 13.1 MB
__device__ float g_buf2[32 * 50 * 16 * 16];    //  1.6 MB
__device__ float g_bufM[16 * 50 * 16 * 16];    //  0.8 MB
__device__ float g_buf3[16 * 50 * 32 * 64];    //  6.6 MB
__device__ float g_buf4[16 * 50 * 64 * 256];   // 52.4 MB

// ------------------------- K1: conv1 + pool + relu -------------------------
// grid (4 rowchunks, 50 c_out, 32 batch), block 256 (thread = output column)
__global__ void k1_conv_pool(const float* __restrict__ x,
                             const float* __restrict__ w1,
                             const float* __restrict__ b1) {
    const int chunk = blockIdx.x;          // 16 conv rows per chunk
    const int co    = blockIdx.y;
    const int b     = blockIdx.z;
    const int j     = threadIdx.x;         // 0..255
    const int k0    = chunk * 16;

    __shared__ float sm[18][256];
    __shared__ float wt[21];

    const float* img = x + b * 64 * 256;
    for (int e = threadIdx.x; e < 18 * 256; e += 256) {
        int er = e >> 8, ec = e & 255;
        int r  = (k0 - 2 + er) & 63;
        sm[er][ec] = img[r * 256 + ec];
    }
    if (threadIdx.x < 21) wt[threadIdx.x] = w1[co * 21 + threadIdx.x];
    __syncthreads();

    float acc[16];
#pragma unroll
    for (int i = 0; i < 16; i++) acc[i] = 0.f;

#pragma unroll
    for (int e = 0; e < 18; e++) {
#pragma unroll
        for (int q = 0; q < 7; q++) {
            float v = sm[e][(j - q) & 255];
#pragma unroll
            for (int p = 0; p < 3; p++) {
                int il = e - 2 + p;            // output row (local)
                if (il >= 0 && il < 16) acc[il] += v * wt[p * 7 + q];
            }
        }
    }

    const float bias = b1[co];
    float* out = g_buf1 + ((size_t)(b * 50 + co) * 32 + (k0 >> 1)) * 64;
#pragma unroll
    for (int pr = 0; pr < 8; pr++) {
        float m = fmaxf(acc[2 * pr], acc[2 * pr + 1]);
        m = fmaxf(m, __shfl_xor_sync(0xffffffffu, m, 1));
        m = fmaxf(m, __shfl_xor_sync(0xffffffffu, m, 2));
        if ((j & 3) == 0) out[pr * 64 + (j >> 2)] = fmaxf(m + bias, 0.f);
    }
}

// ------------------------- K2: conv2 + pool + relu -------------------------
// Full-height accumulators: each input row feeds 3 output rows -> 3 FMA/LDS.
// grid (25 co-pairs, 32 batch), block 128: j = t&63 (column), g = t>>6 (co).
__global__ void k2_conv_pool(const float* __restrict__ w2,
                             const float* __restrict__ b2) {
    const int b  = blockIdx.y;
    const int j  = threadIdx.x & 63;
    const int g  = threadIdx.x >> 6;
    const int co = blockIdx.x * 2 + g;

    __shared__ float sm[32][64];
    __shared__ float sw[2][1050];          // 50 ci * 21 taps, per c_out

    for (int idx = threadIdx.x; idx < 2 * 1050; idx += 128) {
        int gg = idx / 1050, k = idx - gg * 1050;
        sw[gg][k] = w2[(blockIdx.x * 2 + gg) * 1050 + k];
    }

    float acc[32];
#pragma unroll
    for (int r = 0; r < 32; r++) acc[r] = 0.f;

    const float* base = g_buf1 + (size_t)b * 50 * 2048;
    for (int ci = 0; ci < 50; ci++) {
        __syncthreads();
        for (int idx = threadIdx.x; idx < 2048; idx += 128)
            sm[idx >> 6][idx & 63] = base[ci * 2048 + idx];
        __syncthreads();

        float wr[21];
#pragma unroll
        for (int k = 0; k < 21; k++) wr[k] = sw[g][ci * 21 + k];

        for (int q = 0; q < 7; q++) {
            int jq = (j - q) & 63;
#pragma unroll
            for (int r = 0; r < 32; r++) {
                float v = sm[r][jq];
                acc[r]            += v * wr[q];
                acc[(r + 1) & 31] += v * wr[7 + q];
                acc[(r + 2) & 31] += v * wr[14 + q];
            }
        }
    }

    const float bias = b2[co];
    float* out = g_buf2 + (size_t)(b * 50 + co) * 256;
#pragma unroll
    for (int pr = 0; pr < 16; pr++) {
        float m = fmaxf(acc[2 * pr], acc[2 * pr + 1]);
        m = fmaxf(m, __shfl_xor_sync(0xffffffffu, m, 1));
        m = fmaxf(m, __shfl_xor_sync(0xffffffffu, m, 2));
        if ((j & 3) == 0) out[pr * 16 + (j >> 2)] = fmaxf(m + bias, 0.f);
    }
}

// ---------------- merge: out[b] = s[2b] + mean(s[2b+1]) --------------------
// grid (50 co, 16 batch), block 256 (one thread per spatial position)
__global__ void k_merge() {
    const int co = blockIdx.x;
    const int b  = blockIdx.y;
    const int t  = threadIdx.x;

    const float* s0 = g_buf2 + (size_t)((2 * b) * 50 + co) * 256;
    const float* s1 = g_buf2 + (size_t)((2 * b + 1) * 50 + co) * 256;

    float v0 = s0[t];
    float v1 = s1[t];

    __shared__ float red[8];
    float s = v1;
#pragma unroll
    for (int o = 16; o; o >>= 1) s += __shfl_xor_sync(0xffffffffu, s, o);
    if ((t & 31) == 0) red[t >> 5] = s;
    __syncthreads();
    if (t < 32) {
        float ss = (t < 8) ? red[t] : 0.f;
#pragma unroll
        for (int o = 4; o; o >>= 1) ss += __shfl_xor_sync(0xffffffffu, ss, o);
        if (t == 0) red[0] = ss;
    }
    __syncthreads();
    const float mean = red[0] * (1.f / 256.f);

    g_bufM[(size_t)(b * 50 + co) * 256 + t] = v0 + mean;
}

// ---------------- K3: zero-upsample(2,4) + conv3(3x5) + relu ---------------
// Entire 50x16x16 input lives in smem. Only taps with p==i(mod2), q==j(mod4).
// grid (50 co, 16 batch), block 256: j = t&63 (col), g = t>>6 (rows g*8..g*8+7)
__global__ void k3_upconv(const float* __restrict__ w3,
                          const float* __restrict__ b3) {
    const int co = blockIdx.x;
    const int b  = blockIdx.y;
    const int t  = threadIdx.x;
    const int j  = t & 63;
    const int g  = t >> 6;

    extern __shared__ float dyn[];
    float* s  = dyn;             // [50][16][16]
    float* wt = dyn + 50 * 256;  // [50][3][5]

    const float* src = g_bufM + (size_t)b * 50 * 256;
    for (int i = t; i < 12800; i += 256) s[i] = src[i];
    for (int i = t; i < 750;   i += 256) wt[i] = w3[co * 750 + i];
    __syncthreads();

    const int  q1   = j & 3;
    const int  c1   = j >> 2;            // 0..15
    const int  c2   = (c1 - 1) & 15;
    const bool hasB = (q1 == 0);         // kw=5: second tap q=4 only if q1==0

    float acc[8];
#pragma unroll
    for (int k = 0; k < 8; k++) acc[k] = 0.f;

    for (int ci = 0; ci < 50; ci++) {
        const float* sp = s + ci * 256;
        const float* wp = wt + ci * 15;
        float wA0 = wp[q1],      wB0 = hasB ? wp[4]  : 0.f;
        float wA1 = wp[5 + q1],  wB1 = hasB ? wp[9]  : 0.f;
        float wA2 = wp[10 + q1], wB2 = hasB ? wp[14] : 0.f;
#pragma unroll
        for (int k = 0; k < 8; k++) {
            int i = g * 8 + k;
            if ((k & 1) == 0) {          // even output row: p in {0,2}
                int m0 = i >> 1;
                int m2 = (m0 - 1) & 15;
                acc[k] += sp[m0 * 16 + c1] * wA0 + sp[m0 * 16 + c2] * wB0
                        + sp[m2 * 16 + c1] * wA2 + sp[m2 * 16 + c2] * wB2;
            } else {                     // odd output row: p = 1
                int m1 = i >> 1;
                acc[k] += sp[m1 * 16 + c1] * wA1 + sp[m1 * 16 + c2] * wB1;
            }
        }
    }

    const float bias = b3[co];
    float* out = g_buf3 + ((size_t)(b * 50 + co) * 32 + g * 8) * 64;
#pragma unroll
    for (int k = 0; k < 8; k++) out[k * 64 + j] = fmaxf(acc[k] + bias, 0.f);
}

// ---------------- K4: zero-upsample(2,4) + conv4(3x7) + relu ---------------
// Input-row-driven: each small-grid input row feeds 3 output rows.
// grid (4 rowchunks, 50 co, 16 batch), block 256 (thread = output column)
__global__ void k4_upconv(const float* __restrict__ w4,
                          const float* __restrict__ b4) {
    const int chunk = blockIdx.x;
    const int co    = blockIdx.y;
    const int b     = blockIdx.z;
    const int j     = threadIdx.x;       // 0..255
    const int k0    = chunk * 16;

    __shared__ float sm[9][64];
    __shared__ float wt[1050];

    const float* src = g_buf3 + (size_t)b * 50 * 2048;
    for (int i = threadIdx.x; i < 1050; i += 256) wt[i] = w4[co * 1050 + i];

    const int  q1    = j & 3;
    const int  c1    = j >> 2;           // 0..63
    const int  c2    = (c1 - 1) & 63;
    const bool hasB  = (q1 < 3);         // kw=7: second tap q=q1+4 if q1<=2
    const int  mbase = (k0 >> 1) - 1;

    float acc[16];
#pragma unroll
    for (int k = 0; k < 16; k++) acc[k] = 0.f;

    for (int ci = 0; ci < 50; ci++) {
        __syncthreads();
        for (int i = threadIdx.x; i < 9 * 64; i += 256) {
            int e = i >> 6, c = i & 63;
            int mm = (mbase + e) & 31;
            sm[e][c] = src[ci * 2048 + mm * 64 + c];
        }
        __syncthreads();

        float wA[3], wB[3];
#pragma unroll
        for (int p = 0; p < 3; p++) {
            wA[p] = wt[ci * 21 + p * 7 + q1];
            wB[p] = hasB ? wt[ci * 21 + p * 7 + q1 + 4] : 0.f;
        }
#pragma unroll
        for (int e = 0; e < 9; e++) {
            float v1 = sm[e][c1], v2 = sm[e][c2];
#pragma unroll
            for (int p = 0; p < 3; p++) {
                int il = 2 * e - 2 + p;  // output row (local)
                if (il >= 0 && il < 16)
                    acc[il] += v1 * wA[p] + v2 * wB[p];
            }
        }
    }

    const float bias = b4[co];
    float* out = g_buf4 + ((size_t)(b * 50 + co) * 64 + k0) * 256;
#pragma unroll
    for (int k = 0; k < 16; k++) out[k * 256 + j] = fmaxf(acc[k] + bias, 0.f);
}

// ---------------------- K5: conv5 (50 -> 1) + sigmoid ----------------------
// grid (16 rowchunks of 4, 16 batch), block 256 (thread = output column)
__global__ void k5_conv_sig(const float* __restrict__ w5,
                            const float* __restrict__ b5,
                            float* __restrict__ out) {
    const int chunk = blockIdx.x;
    const int b     = blockIdx.y;
    const int j     = threadIdx.x;
    const int k0    = chunk * 4;

    __shared__ float sm[6][256];
    __shared__ float wt[1050];

    const float* src = g_buf4 + (size_t)b * 50 * 16384;
    for (int i = threadIdx.x; i < 1050; i += 256) wt[i] = w5[i];

    float acc[4] = {0.f, 0.f, 0.f, 0.f};

    for (int ci = 0; ci < 50; ci++) {
        __syncthreads();
#pragma unroll
        for (int e = 0; e < 6; e++) {
            int r = (k0 - 2 + e) & 63;
            sm[e][j] = src[ci * 16384 + r * 256 + j];
        }
        __syncthreads();

        float wr[21];
#pragma unroll
        for (int k = 0; k < 21; k++) wr[k] = wt[ci * 21 + k];

#pragma unroll
        for (int e = 0; e < 6; e++) {
#pragma unroll
            for (int q = 0; q < 7; q++) {
                float v = sm[e][(j - q) & 255];
#pragma unroll
                for (int p = 0; p < 3; p++) {
                    int il = e - 2 + p;
                    if (il >= 0 && il < 4) acc[il] += v * wr[p * 7 + q];
                }
            }
        }
    }

    const float bias = b5[0];
#pragma unroll
    for (int k = 0; k < 4; k++) {
        float v = acc[k] + bias;
        out[(size_t)(b * 64 + k0 + k) * 256 + j] = 1.f / (1.f + __expf(-v));
    }
}

// ---------------------------------------------------------------------------
extern "C" void kernel_launch(void* const* d_in, const int* in_sizes, int n_in,
                              void* d_out, int out_size) {
    (void)in_sizes; (void)n_in; (void)out_size;
    const float* x  = (const float*)d_in[0];
    const float* w1 = (const float*)d_in[1];
    const float* b1 = (const float*)d_in[2];
    const float* w2 = (const float*)d_in[3];
    const float* b2 = (const float*)d_in[4];
    const float* w3 = (const float*)d_in[5];
    const float* b3 = (const float*)d_in[6];
    const float* w4 = (const float*)d_in[7];
    const float* b4 = (const float*)d_in[8];
    const float* w5 = (const float*)d_in[9];
    const float* b5 = (const float*)d_in[10];
    float* out = (float*)d_out;

    const int k3_smem = (50 * 256 + 750) * (int)sizeof(float);  // 54200 B
    cudaFuncSetAttribute(k3_upconv,
                         cudaFuncAttributeMaxDynamicSharedMemorySize, k3_smem);

    k1_conv_pool<<<dim3(4, 50, 32), 256>>>(x, w1, b1);
    k2_conv_pool<<<dim3(25, 32), 128>>>(w2, b2);
    k_merge<<<dim3(50, 16), 256>>>();
    k3_upconv<<<dim3(50, 16), 256, k3_smem>>>(w3, b3);
    k4_upconv<<<dim3(4, 50, 16), 256>>>(w4, b4);
    k5_conv_sig<<<dim3(16, 16), 256>>>(w5, b5, out);
}

// round 2
// speedup vs baseline: 1.6153x; 1.6153x over previous
#include <cuda_runtime.h>
#include <cstdint>

// ---------------------------------------------------------------------------
// Direct circular-convolution Net_CCL, round 2: fma.rn.f32x2 + c_out pairing.
//
//   x      : [16,2,64,256] -> [32,64,256] (c_in = 1)
//   L1: conv w1[50,1,3,7]  + b1, maxpool(2,4), relu   -> buf1 [32,50,32,64]
//   L2: conv w2[50,50,3,7] + b2, maxpool(2,4), relu   -> buf2 [32,50,16,16]
//   merge: out[b] = s[2b] + mean(s[2b+1])             -> bufM [16,50,16,16]
//   L3: upsample(2,4) conv w3[50,50,3,5] + b3, relu   -> buf3 [16,50,32,64]
//   L4: upsample(2,4) conv w4[50,50,3,7] + b4, relu   -> buf4 [16,50,64,256]
//   L5: conv w5[1,50,3,7]  + b5, sigmoid              -> out  [16,64,256]
//
// Circular conv: y[i][j] = sum_{p,q} x[(i-p)%H][(j-q)%W] * w[p][q].
// Upsampled layers read the small tensor directly (taps with matching parity).
// Each thread accumulates a PAIR of output channels in packed f32x2 regs.
// ---------------------------------------------------------------------------

typedef unsigned long long f2;

__device__ __forceinline__ void fma2(f2 &a, f2 v, f2 w) {
    asm("fma.rn.f32x2 %0, %1, %2, %0;" : "+l"(a) : "l"(v), "l"(w));
}
__device__ __forceinline__ f2 pack2(float lo, float hi) {
    f2 r; asm("mov.b64 %0, {%1, %2};" : "=l"(r) : "f"(lo), "f"(hi)); return r;
}
__device__ __forceinline__ float2 unpack2(f2 a) {
    float2 r; asm("mov.b64 {%0, %1}, %2;" : "=f"(r.x), "=f"(r.y) : "l"(a)); return r;
}

__device__ float g_buf1[32 * 50 * 32 * 64];    // 13.1 MB
__device__ float g_buf2[32 * 50 * 16 * 16];    //  1.6 MB
__device__ float g_bufM[16 * 50 * 16 * 16];    //  0.8 MB
__device__ float g_buf3[16 * 50 * 32 * 64];    //  6.6 MB
__device__ float g_buf4[16 * 50 * 64 * 256];   // 52.4 MB

// ------------------------- K1: conv1 + pool + relu -------------------------
// grid (4 rowchunks, 25 co-pairs, 32 batch), block 256 (thread = column).
__global__ void k1_conv_pool(const float* __restrict__ x,
                             const float* __restrict__ w1,
                             const float* __restrict__ b1) {
    const int chunk = blockIdx.x;
    const int co0   = blockIdx.y * 2;
    const int b     = blockIdx.z;
    const int j     = threadIdx.x;
    const int k0    = chunk * 16;

    __shared__ float sm[18][256];
    __shared__ f2 swp[21];

    const float* img = x + b * 64 * 256;
    float4* d4 = reinterpret_cast<float4*>(&sm[0][0]);
    for (int i = threadIdx.x; i < 18 * 64; i += 256) {
        int e = i >> 6, c4 = i & 63;
        int r = (k0 - 2 + e) & 63;
        d4[i] = reinterpret_cast<const float4*>(img + r * 256)[c4];
    }
    if (threadIdx.x < 21)
        swp[threadIdx.x] = pack2(w1[co0 * 21 + threadIdx.x],
                                 w1[(co0 + 1) * 21 + threadIdx.x]);
    __syncthreads();

    f2 acc[16];
#pragma unroll
    for (int i = 0; i < 16; i++) acc[i] = 0ull;

    for (int q = 0; q < 7; q++) {
        f2 wp0 = swp[q], wp1 = swp[7 + q], wp2 = swp[14 + q];
        int jq = (j - q) & 255;
#pragma unroll
        for (int e = 0; e < 18; e++) {
            float v = sm[e][jq];
            f2 vv = pack2(v, v);
#pragma unroll
            for (int p = 0; p < 3; p++) {
                int il = e - 2 + p;
                if (il >= 0 && il < 16)
                    fma2(acc[il], vv, p == 0 ? wp0 : (p == 1 ? wp1 : wp2));
            }
        }
    }

    const float bx0 = b1[co0], bx1 = b1[co0 + 1];
    float* o0 = g_buf1 + ((size_t)(b * 50 + co0) * 32 + (k0 >> 1)) * 64;
    float* o1 = o0 + 32 * 64;
#pragma unroll
    for (int pr = 0; pr < 8; pr++) {
        float2 a = unpack2(acc[2 * pr]);
        float2 c = unpack2(acc[2 * pr + 1]);
        float m0 = fmaxf(a.x, c.x), m1 = fmaxf(a.y, c.y);
        m0 = fmaxf(m0, __shfl_xor_sync(0xffffffffu, m0, 1));
        m0 = fmaxf(m0, __shfl_xor_sync(0xffffffffu, m0, 2));
        m1 = fmaxf(m1, __shfl_xor_sync(0xffffffffu, m1, 1));
        m1 = fmaxf(m1, __shfl_xor_sync(0xffffffffu, m1, 2));
        if ((j & 3) == 0) {
            o0[pr * 64 + (j >> 2)] = fmaxf(m0 + bx0, 0.f);
            o1[pr * 64 + (j >> 2)] = fmaxf(m1 + bx1, 0.f);
        }
    }
}

// ------------------------- K2: conv2 + pool + relu -------------------------
// Full-height accumulators (each v feeds 3 output rows x 2 co = 3 FFMA2/LDS).
// grid (13 pair-duos, 32 batch), block 128: j = t&63 (col), g = t>>6 (pair).
__global__ void k2_conv_pool(const float* __restrict__ w2,
                             const float* __restrict__ b2) {
    const int b = blockIdx.y;
    const int j = threadIdx.x & 63;
    const int g = threadIdx.x >> 6;
    const int pairIdx = blockIdx.x * 2 + g;
    const bool valid = (pairIdx < 25);
    const int pc  = valid ? pairIdx : 24;
    const int co0 = pc * 2;

    __shared__ float sm[32][64];
    __shared__ f2 swp[2][1050];

    for (int idx = threadIdx.x; idx < 2100; idx += 128) {
        int gg = idx / 1050, k = idx - gg * 1050;
        int p2 = blockIdx.x * 2 + gg; if (p2 > 24) p2 = 24;
        swp[gg][k] = pack2(w2[(2 * p2) * 1050 + k], w2[(2 * p2 + 1) * 1050 + k]);
    }

    f2 acc[32];
#pragma unroll
    for (int r = 0; r < 32; r++) acc[r] = 0ull;

    const float* base = g_buf1 + (size_t)b * 50 * 2048;
    for (int ci = 0; ci < 50; ci++) {
        __syncthreads();
        {
            const float4* s4 = reinterpret_cast<const float4*>(base + ci * 2048);
            float4* d4 = reinterpret_cast<float4*>(&sm[0][0]);
#pragma unroll
            for (int i = 0; i < 4; i++) d4[threadIdx.x + i * 128] = s4[threadIdx.x + i * 128];
        }
        __syncthreads();

        const f2* wrow = swp[g] + ci * 21;
#pragma unroll 1
        for (int q = 0; q < 7; q++) {
            f2 w0 = wrow[q], w1 = wrow[7 + q], w2r = wrow[14 + q];
            int jq = (j - q) & 63;
#pragma unroll
            for (int r = 0; r < 32; r++) {
                float v = sm[r][jq];
                f2 vv = pack2(v, v);
                fma2(acc[r], vv, w0);
                fma2(acc[(r + 1) & 31], vv, w1);
                fma2(acc[(r + 2) & 31], vv, w2r);
            }
        }
    }

    const float bx0 = b2[co0], bx1 = b2[co0 + 1];
    float* o0 = g_buf2 + (size_t)(b * 50 + co0) * 256;
    float* o1 = o0 + 256;
#pragma unroll
    for (int pr = 0; pr < 16; pr++) {
        float2 a = unpack2(acc[2 * pr]);
        float2 c = unpack2(acc[2 * pr + 1]);
        float m0 = fmaxf(a.x, c.x), m1 = fmaxf(a.y, c.y);
        m0 = fmaxf(m0, __shfl_xor_sync(0xffffffffu, m0, 1));
        m0 = fmaxf(m0, __shfl_xor_sync(0xffffffffu, m0, 2));
        m1 = fmaxf(m1, __shfl_xor_sync(0xffffffffu, m1, 1));
        m1 = fmaxf(m1, __shfl_xor_sync(0xffffffffu, m1, 2));
        if (valid && (j & 3) == 0) {
            o0[pr * 16 + (j >> 2)] = fmaxf(m0 + bx0, 0.f);
            o1[pr * 16 + (j >> 2)] = fmaxf(m1 + bx1, 0.f);
        }
    }
}

// ---------------- merge: out[b] = s[2b] + mean(s[2b+1]) --------------------
__global__ void k_merge() {
    const int co = blockIdx.x;
    const int b  = blockIdx.y;
    const int t  = threadIdx.x;

    const float* s0 = g_buf2 + (size_t)((2 * b) * 50 + co) * 256;
    const float* s1 = g_buf2 + (size_t)((2 * b + 1) * 50 + co) * 256;

    float v0 = s0[t];
    float v1 = s1[t];

    __shared__ float red[8];
    float s = v1;
#pragma unroll
    for (int o = 16; o; o >>= 1) s += __shfl_xor_sync(0xffffffffu, s, o);
    if ((t & 31) == 0) red[t >> 5] = s;
    __syncthreads();
    if (t < 32) {
        float ss = (t < 8) ? red[t] : 0.f;
#pragma unroll
        for (int o = 4; o; o >>= 1) ss += __shfl_xor_sync(0xffffffffu, ss, o);
        if (t == 0) red[0] = ss;
    }
    __syncthreads();
    const float mean = red[0] * (1.f / 256.f);

    g_bufM[(size_t)(b * 50 + co) * 256 + t] = v0 + mean;
}

// ---------------- K3: zero-upsample(2,4) + conv3(3x5) + relu ---------------
// Whole 50x16x16 input in smem, shared by a co-pair. grid (25, 16), block 256.
__global__ void k3_upconv(const float* __restrict__ w3,
                          const float* __restrict__ b3) {
    const int co0 = blockIdx.x * 2;
    const int b   = blockIdx.y;
    const int t   = threadIdx.x;
    const int j   = t & 63;
    const int g   = t >> 6;

    extern __shared__ float dyn[];
    float* s  = dyn;                                   // [50][256]
    f2*    wp = reinterpret_cast<f2*>(dyn + 12800);    // [50][15]

    const float* src = g_bufM + (size_t)b * 50 * 256;
    {
        const float4* s4 = reinterpret_cast<const float4*>(src);
        float4* d4 = reinterpret_cast<float4*>(s);
        for (int i = t; i < 3200; i += 256) d4[i] = s4[i];
    }
    for (int i = t; i < 750; i += 256)
        wp[i] = pack2(w3[co0 * 750 + i], w3[(co0 + 1) * 750 + i]);
    __syncthreads();

    const int  q1   = j & 3;
    const int  c1   = j >> 2;
    const int  c2   = (c1 - 1) & 15;
    const bool hasB = (q1 == 0);

    f2 acc[8];
#pragma unroll
    for (int k = 0; k < 8; k++) acc[k] = 0ull;

    for (int ci = 0; ci < 50; ci++) {
        const float* sp = s + ci * 256;
        const f2* wr = wp + ci * 15;
        f2 wA0 = wr[q1],      wB0 = hasB ? wr[4]  : 0ull;
        f2 wA1 = wr[5 + q1],  wB1 = hasB ? wr[9]  : 0ull;
        f2 wA2 = wr[10 + q1], wB2 = hasB ? wr[14] : 0ull;
#pragma unroll
        for (int k = 0; k < 8; k++) {
            int i = g * 8 + k;
            if ((k & 1) == 0) {           // even row: p in {0,2}
                int m0 = i >> 1;
                int m2 = (m0 - 1) & 15;
                float a0 = sp[m0 * 16 + c1], a1 = sp[m0 * 16 + c2];
                float a2 = sp[m2 * 16 + c1], a3 = sp[m2 * 16 + c2];
                fma2(acc[k], pack2(a0, a0), wA0);
                fma2(acc[k], pack2(a1, a1), wB0);
                fma2(acc[k], pack2(a2, a2), wA2);
                fma2(acc[k], pack2(a3, a3), wB2);
            } else {                      // odd row: p = 1
                int m1 = i >> 1;
                float a0 = sp[m1 * 16 + c1], a1 = sp[m1 * 16 + c2];
                fma2(acc[k], pack2(a0, a0), wA1);
                fma2(acc[k], pack2(a1, a1), wB1);
            }
        }
    }

    const float bx0 = b3[co0], bx1 = b3[co0 + 1];
    float* o0 = g_buf3 + ((size_t)(b * 50 + co0) * 32 + g * 8) * 64;
    float* o1 = o0 + 32 * 64;
#pragma unroll
    for (int k = 0; k < 8; k++) {
        float2 a = unpack2(acc[k]);
        o0[k * 64 + j] = fmaxf(a.x + bx0, 0.f);
        o1[k * 64 + j] = fmaxf(a.y + bx1, 0.f);
    }
}

// ---------------- K4: zero-upsample(2,4) + conv4(3x7) + relu ---------------
// grid (4 rowchunks, 25 co-pairs, 16 batch), block 256 (thread = column).
__global__ void k4_upconv(const float* __restrict__ w4,
                          const float* __restrict__ b4) {
    const int chunk = blockIdx.x;
    const int co0   = blockIdx.y * 2;
    const int b     = blockIdx.z;
    const int j     = threadIdx.x;
    const int k0    = chunk * 16;

    __shared__ float sm[9][64];
    __shared__ f2 swp[1050];

    for (int i = threadIdx.x; i < 1050; i += 256)
        swp[i] = pack2(w4[co0 * 1050 + i], w4[(co0 + 1) * 1050 + i]);

    const int  q1    = j & 3;
    const int  c1    = j >> 2;
    const int  c2    = (c1 - 1) & 63;
    const bool hasB  = (q1 < 3);
    const int  mbase = (k0 >> 1) - 1;

    f2 acc[16];
#pragma unroll
    for (int k = 0; k < 16; k++) acc[k] = 0ull;

    const float* src = g_buf3 + (size_t)b * 50 * 2048;
    for (int ci = 0; ci < 50; ci++) {
        __syncthreads();
        if (threadIdx.x < 144) {
            int e = threadIdx.x >> 4, c4 = threadIdx.x & 15;
            int mm = (mbase + e) & 31;
            reinterpret_cast<float4*>(&sm[0][0])[threadIdx.x] =
                reinterpret_cast<const float4*>(src + ci * 2048 + mm * 64)[c4];
        }
        __syncthreads();

        const f2* wr = swp + ci * 21;
        f2 wA[3], wB[3];
#pragma unroll
        for (int p = 0; p < 3; p++) {
            wA[p] = wr[p * 7 + q1];
            wB[p] = hasB ? wr[p * 7 + q1 + 4] : 0ull;
        }
#pragma unroll
        for (int e = 0; e < 9; e++) {
            float v1 = sm[e][c1], v2 = sm[e][c2];
            f2 vv1 = pack2(v1, v1), vv2 = pack2(v2, v2);
#pragma unroll
            for (int p = 0; p < 3; p++) {
                int il = 2 * e - 2 + p;
                if (il >= 0 && il < 16) {
                    fma2(acc[il], vv1, wA[p]);
                    fma2(acc[il], vv2, wB[p]);
                }
            }
        }
    }

    const float bx0 = b4[co0], bx1 = b4[co0 + 1];
    float* o0 = g_buf4 + ((size_t)(b * 50 + co0) * 64 + k0) * 256;
    float* o1 = o0 + 64 * 256;
#pragma unroll
    for (int k = 0; k < 16; k++) {
        float2 a = unpack2(acc[k]);
        o0[k * 256 + j] = fmaxf(a.x + bx0, 0.f);
        o1[k * 256 + j] = fmaxf(a.y + bx1, 0.f);
    }
}

// ---------------------- K5: conv5 (50 -> 1) + sigmoid ----------------------
// Row-pair packed accumulators (pairs of adjacent output rows in f32x2),
// padded weight pairs prebuilt in smem; register prefetch of next ci tile.
// grid (8 rowchunks of 8, 16 batch), block 256 (thread = column).
__global__ void k5_conv_sig(const float* __restrict__ w5,
                            const float* __restrict__ b5,
                            float* __restrict__ out) {
    const int chunk = blockIdx.x;
    const int b     = blockIdx.y;
    const int j     = threadIdx.x;
    const int k0    = chunk * 8;

    __shared__ float sm[10][256];
    __shared__ f2 wpad[50][28];   // [ci][q*4 + d]

    for (int i = threadIdx.x; i < 1400; i += 256) {
        int ci = i / 28, r = i - ci * 28;
        int q = r >> 2, d = r & 3;
        int plo = 2 - d, phi = 3 - d;
        float lo = (plo >= 0 && plo <= 2) ? w5[ci * 21 + plo * 7 + q] : 0.f;
        float hi = (phi >= 0 && phi <= 2) ? w5[ci * 21 + phi * 7 + q] : 0.f;
        wpad[ci][r] = pack2(lo, hi);
    }

    f2 acc[4] = {0ull, 0ull, 0ull, 0ull};
    const float* src = g_buf4 + (size_t)b * 50 * 16384;

    float4 st[3];
    auto load_ci = [&](int ci) {
#pragma unroll
        for (int u = 0; u < 3; u++) {
            int i = j + u * 256;
            if (i < 640) {
                int e = i >> 6, c4 = i & 63;
                int r = (k0 - 2 + e) & 63;
                st[u] = reinterpret_cast<const float4*>(src + ci * 16384 + r * 256)[c4];
            }
        }
    };
    load_ci(0);

    for (int ci = 0; ci < 50; ci++) {
        __syncthreads();
#pragma unroll
        for (int u = 0; u < 3; u++) {
            int i = j + u * 256;
            if (i < 640) reinterpret_cast<float4*>(&sm[0][0])[i] = st[u];
        }
        __syncthreads();
        if (ci + 1 < 50) load_ci(ci + 1);

#pragma unroll 1
        for (int q = 0; q < 7; q++) {
            const f2* wd = &wpad[ci][q * 4];
            f2 w0 = wd[0], w1 = wd[1], w2r = wd[2], w3r = wd[3];
            int jq = (j - q) & 255;
#pragma unroll
            for (int e = 0; e < 10; e++) {
                float v = sm[e][jq];
                f2 vv = pack2(v, v);
                int P1 = e >> 1;
                if (P1 < 4) fma2(acc[P1], vv, (e & 1) ? w1 : w0);
                int P2 = P1 - 1;
                if (P2 >= 0) fma2(acc[P2], vv, (e & 1) ? w3r : w2r);
            }
        }
    }

    const float bias = b5[0];
#pragma unroll
    for (int P = 0; P < 4; P++) {
        float2 a = unpack2(acc[P]);
        float v0 = a.x + bias, v1 = a.y + bias;
        out[(size_t)(b * 64 + k0 + 2 * P) * 256 + j]     = 1.f / (1.f + __expf(-v0));
        out[(size_t)(b * 64 + k0 + 2 * P + 1) * 256 + j] = 1.f / (1.f + __expf(-v1));
    }
}

// ---------------------------------------------------------------------------
extern "C" void kernel_launch(void* const* d_in, const int* in_sizes, int n_in,
                              void* d_out, int out_size) {
    (void)in_sizes; (void)n_in; (void)out_size;
    const float* x  = (const float*)d_in[0];
    const float* w1 = (const float*)d_in[1];
    const float* b1 = (const float*)d_in[2];
    const float* w2 = (const float*)d_in[3];
    const float* b2 = (const float*)d_in[4];
    const float* w3 = (const float*)d_in[5];
    const float* b3 = (const float*)d_in[6];
    const float* w4 = (const float*)d_in[7];
    const float* b4 = (const float*)d_in[8];
    const float* w5 = (const float*)d_in[9];
    const float* b5 = (const float*)d_in[10];
    float* out = (float*)d_out;

    const int k3_smem = 12800 * 4 + 750 * 8;   // 57200 B
    cudaFuncSetAttribute(k3_upconv,
                         cudaFuncAttributeMaxDynamicSharedMemorySize, k3_smem);

    k1_conv_pool<<<dim3(4, 25, 32), 256>>>(x, w1, b1);
    k2_conv_pool<<<dim3(13, 32), 128>>>(w2, b2);
    k_merge<<<dim3(50, 16), 256>>>();
    k3_upconv<<<dim3(25, 16), 256, k3_smem>>>(w3, b3);
    k4_upconv<<<dim3(4, 25, 16), 256>>>(w4, b4);
    k5_conv_sig<<<dim3(8, 16), 256>>>(w5, b5, out);
}